// round 1
// baseline (speedup 1.0000x reference)
#include <cuda_runtime.h>
#include <cuda_bf16.h>
#include <math.h>

#define B_    2
#define C_    512
#define C3_   1536
#define H_    128
#define W_    128
#define HW_   16384
#define HEADS_ 64
#define CH_   8
#define PLANE_ (C3_ * HW_)          // 25,165,824 floats per (mod,b)
#define TENSOR_ ((size_t)B_ * C_ * HW_)  // 16,777,216 floats per output tensor

// ---------------- scratch (device globals; no allocations) ----------------
__device__ float g_conv[4][PLANE_];          // conv1x1 output, index mb = mod*2+b
__device__ float g_dw[4][PLANE_];            // depthwise output, index mb
__device__ float g_sumsq[2][B_][2][C_];      // [mod][b][q=0/k=1][ch]
__device__ float g_attn[2][B_][HEADS_][64];  // attn1/attn2 (after temp scale)
__device__ float g_a[2][B_][HEADS_][64];     // softmaxed attention

// ---------------- K1: 1x1 conv as GEMM  Y[o,n] = sum_i W[o,i] X[i,n] + b[o] ----
// BM=BN=128, BK=8, 256 threads, 8x8 per thread
__global__ __launch_bounds__(256) void k_gemm(
    const float* __restrict__ hsi, const float* __restrict__ lidar,
    const float* __restrict__ hw_w, const float* __restrict__ hw_b,
    const float* __restrict__ lw_w, const float* __restrict__ lw_b)
{
    int mb  = blockIdx.z;           // 0..3 : mod*2+b
    int mod = mb >> 1, bb = mb & 1;
    const float* Wm   = mod ? lw_w : hw_w;
    const float* bias = mod ? lw_b : hw_b;
    const float* X = (mod ? lidar : hsi) + (size_t)bb * C_ * HW_;
    float* Y = g_conv[mb];

    int m0 = blockIdx.y * 128;
    int n0 = blockIdx.x * 128;
    __shared__ float As[8][128];
    __shared__ float Bs[8][128];
    int tid = threadIdx.x;
    int tm = (tid >> 4) * 8;
    int tn = (tid & 15) * 8;
    float acc[8][8] = {};

    int am = tid >> 1;            // 0..127  (m within tile)
    int ak = (tid & 1) * 4;       // 0 or 4  (k within tile)
    int bk = tid >> 5;            // 0..7
    int bn = (tid & 31) * 4;      // 0..124

    for (int k0 = 0; k0 < C_; k0 += 8) {
        float4 av = *(const float4*)&Wm[(size_t)(m0 + am) * C_ + k0 + ak];
        float4 bv = *(const float4*)&X[(size_t)(k0 + bk) * HW_ + n0 + bn];
        As[ak + 0][am] = av.x;
        As[ak + 1][am] = av.y;
        As[ak + 2][am] = av.z;
        As[ak + 3][am] = av.w;
        *(float4*)&Bs[bk][bn] = bv;
        __syncthreads();
        #pragma unroll
        for (int k = 0; k < 8; k++) {
            float4 a0 = *(const float4*)&As[k][tm];
            float4 a1 = *(const float4*)&As[k][tm + 4];
            float4 b0 = *(const float4*)&Bs[k][tn];
            float4 b1 = *(const float4*)&Bs[k][tn + 4];
            float af[8] = {a0.x, a0.y, a0.z, a0.w, a1.x, a1.y, a1.z, a1.w};
            float bf[8] = {b0.x, b0.y, b0.z, b0.w, b1.x, b1.y, b1.z, b1.w};
            #pragma unroll
            for (int i = 0; i < 8; i++)
                #pragma unroll
                for (int j = 0; j < 8; j++)
                    acc[i][j] += af[i] * bf[j];
        }
        __syncthreads();
    }
    #pragma unroll
    for (int i = 0; i < 8; i++) {
        float bi = bias[m0 + tm + i];
        #pragma unroll
        for (int j = 0; j < 8; j++) acc[i][j] += bi;
        float* yp = &Y[(size_t)(m0 + tm + i) * HW_ + n0 + tn];
        *(float4*)yp       = make_float4(acc[i][0], acc[i][1], acc[i][2], acc[i][3]);
        *(float4*)(yp + 4) = make_float4(acc[i][4], acc[i][5], acc[i][6], acc[i][7]);
    }
}

// ---------------- K2: depthwise 3x3 (SAME, zero pad) + per-channel sum of squares ---
// one block (128 threads, one per x-column) per (mod,b,channel) plane
__global__ __launch_bounds__(128) void k_dw(
    const float* __restrict__ hdww, const float* __restrict__ hdwb,
    const float* __restrict__ ldww, const float* __restrict__ ldwb)
{
    int idx = blockIdx.x;          // mb*1536 + o
    int o   = idx % C3_;
    int mb  = idx / C3_;
    int mod = mb >> 1;
    const float* src = g_conv[mb] + (size_t)o * HW_;
    float*       dst = g_dw[mb]   + (size_t)o * HW_;
    const float* wp  = (mod ? ldww : hdww) + o * 9;
    float w[9];
    #pragma unroll
    for (int t = 0; t < 9; t++) w[t] = __ldg(&wp[t]);
    float bias = (mod ? ldwb : hdwb)[o];

    int x = threadIdx.x;  // 0..127
    bool xl = x > 0, xr = x < 127;
    float rm1[3] = {0.f, 0.f, 0.f};
    float r0[3], r1[3];
    r0[0] = xl ? src[x - 1] : 0.f;
    r0[1] = src[x];
    r0[2] = xr ? src[x + 1] : 0.f;
    float ssq = 0.f;
    for (int y = 0; y < H_; y++) {
        if (y < H_ - 1) {
            const float* s = src + (y + 1) * W_;
            r1[0] = xl ? s[x - 1] : 0.f;
            r1[1] = s[x];
            r1[2] = xr ? s[x + 1] : 0.f;
        } else {
            r1[0] = r1[1] = r1[2] = 0.f;
        }
        float v = bias
                + w[0] * rm1[0] + w[1] * rm1[1] + w[2] * rm1[2]
                + w[3] * r0[0]  + w[4] * r0[1]  + w[5] * r0[2]
                + w[6] * r1[0]  + w[7] * r1[1]  + w[8] * r1[2];
        dst[y * W_ + x] = v;
        ssq += v * v;
        rm1[0] = r0[0]; rm1[1] = r0[1]; rm1[2] = r0[2];
        r0[0]  = r1[0]; r0[1]  = r1[1]; r0[2]  = r1[2];
    }
    if (o < 2 * C_) {   // q (0..511) and k (512..1023) need l2-norm sums
        #pragma unroll
        for (int off = 16; off; off >>= 1)
            ssq += __shfl_down_sync(0xffffffffu, ssq, off);
        __shared__ float sw[4];
        if ((x & 31) == 0) sw[x >> 5] = ssq;
        __syncthreads();
        if (x == 0) {
            float t = sw[0] + sw[1] + sw[2] + sw[3];
            g_sumsq[mod][mb & 1][(o >= C_) ? 1 : 0][o & (C_ - 1)] = t;
        }
    }
}

// ---------------- K3: channel attention  attn[c,d] = temp * qk / (|q_c||k_d|) -------
// grid: (head, b, attn-id). attn0: q=hsi,k=lidar ; attn1: q=lidar,k=hsi
__global__ __launch_bounds__(256) void k_attn(
    const float* __restrict__ temp1, const float* __restrict__ temp2)
{
    int h = blockIdx.x, bb = blockIdx.y, a = blockIdx.z;
    int qmod = a, kmod = 1 - a;
    const float* q  = g_dw[qmod * 2 + bb] + (size_t)(h * CH_) * HW_;
    const float* kk = g_dw[kmod * 2 + bb] + (size_t)(C_ + h * CH_) * HW_;
    int tid = threadIdx.x;
    float acc[8][8] = {};
    for (int n = tid; n < HW_; n += 256) {
        float qv[8], kv[8];
        #pragma unroll
        for (int c = 0; c < 8; c++) {
            qv[c] = q[(size_t)c * HW_ + n];
            kv[c] = kk[(size_t)c * HW_ + n];
        }
        #pragma unroll
        for (int c = 0; c < 8; c++)
            #pragma unroll
            for (int d = 0; d < 8; d++)
                acc[c][d] += qv[c] * kv[d];
    }
    __shared__ float red[8][64];
    int lane = tid & 31, wid = tid >> 5;
    #pragma unroll
    for (int c = 0; c < 8; c++)
        #pragma unroll
        for (int d = 0; d < 8; d++) {
            float v = acc[c][d];
            #pragma unroll
            for (int off = 16; off; off >>= 1)
                v += __shfl_down_sync(0xffffffffu, v, off);
            if (lane == 0) red[wid][c * 8 + d] = v;
        }
    __syncthreads();
    if (tid < 64) {
        float s = 0.f;
        #pragma unroll
        for (int wg = 0; wg < 8; wg++) s += red[wg][tid];   // fixed order -> deterministic
        int c = tid >> 3, d = tid & 7;
        float qn = fmaxf(sqrtf(g_sumsq[qmod][bb][0][h * CH_ + c]), 1e-12f);
        float kn = fmaxf(sqrtf(g_sumsq[kmod][bb][1][h * CH_ + d]), 1e-12f);
        float tmp = (a == 0 ? temp1 : temp2)[h];
        g_attn[a][bb][h][tid] = s / (qn * kn) * tmp;
    }
}

// ---------------- K4: score fusion conv + BN(eval) + ReLU + softmax(+attn) ---------
// grid: (o=64, b=2), 64 threads = (c,d)
__global__ __launch_bounds__(64) void k_fuse(
    const float* __restrict__ projw, const float* __restrict__ projb,
    const float* __restrict__ gamma, const float* __restrict__ beta,
    const float* __restrict__ mean,  const float* __restrict__ var)
{
    int o = blockIdx.x, bb = blockIdx.y;
    int tid = threadIdx.x;   // c*8+d
    float s = projb[o];
    const float* w = projw + o * 128;
    #pragma unroll 8
    for (int i = 0; i < 64; i++) s += w[i]      * g_attn[0][bb][i][tid];
    #pragma unroll 8
    for (int i = 0; i < 64; i++) s += w[64 + i] * g_attn[1][bb][i][tid];
    s = (s - mean[o]) * rsqrtf(var[o] + 1e-5f) * gamma[o] + beta[o];
    s = fmaxf(s, 0.f);
    #pragma unroll
    for (int a = 0; a < 2; a++) {
        float v = s + g_attn[a][bb][o][tid];
        float m = v;
        #pragma unroll
        for (int off = 4; off; off >>= 1)
            m = fmaxf(m, __shfl_xor_sync(0xffffffffu, m, off, 8));
        float e = expf(v - m);
        float su = e;
        #pragma unroll
        for (int off = 4; off; off >>= 1)
            su += __shfl_xor_sync(0xffffffffu, su, off, 8);
        g_a[a][bb][o][tid] = e / su;
    }
}

// ---------------- K5: out = a @ v + v + x  (both modalities) -----------------------
// grid: (n-tile=64, b*head=128, mod=2)
__global__ __launch_bounds__(256) void k_out(
    const float* __restrict__ hsi, const float* __restrict__ lidar,
    float* __restrict__ out)
{
    int mod = blockIdx.z;
    int bh  = blockIdx.y;
    int bb  = bh >> 6, h = bh & 63;
    int n   = blockIdx.x * 256 + threadIdx.x;
    __shared__ float a_s[64];
    if (threadIdx.x < 64)
        a_s[threadIdx.x] = g_a[mod][bb][h][threadIdx.x];
    __syncthreads();
    const float* v = g_dw[mod * 2 + bb] + (size_t)(2 * C_ + h * CH_) * HW_;
    const float* x = (mod ? lidar : hsi) + (size_t)(bb * C_ + h * CH_) * HW_;
    float* op = out + (size_t)mod * TENSOR_ + (size_t)(bb * C_ + h * CH_) * HW_;
    float vv[8];
    #pragma unroll
    for (int d = 0; d < 8; d++) vv[d] = v[(size_t)d * HW_ + n];
    #pragma unroll
    for (int c = 0; c < 8; c++) {
        float s = vv[c] + x[(size_t)c * HW_ + n];
        #pragma unroll
        for (int d = 0; d < 8; d++) s += a_s[c * 8 + d] * vv[d];
        op[(size_t)c * HW_ + n] = s;
    }
}

// ---------------- launch -----------------------------------------------------------
extern "C" void kernel_launch(void* const* d_in, const int* in_sizes, int n_in,
                              void* d_out, int out_size)
{
    const float* hsi    = (const float*)d_in[0];
    const float* lidar  = (const float*)d_in[1];
    const float* hqkvw  = (const float*)d_in[2];
    const float* hqkvb  = (const float*)d_in[3];
    const float* lqkvw  = (const float*)d_in[4];
    const float* lqkvb  = (const float*)d_in[5];
    const float* hdww   = (const float*)d_in[6];
    const float* hdwb   = (const float*)d_in[7];
    const float* ldww   = (const float*)d_in[8];
    const float* ldwb   = (const float*)d_in[9];
    const float* temp1  = (const float*)d_in[10];
    const float* temp2  = (const float*)d_in[11];
    const float* projw  = (const float*)d_in[12];
    const float* projb  = (const float*)d_in[13];
    const float* gamma  = (const float*)d_in[14];
    const float* beta   = (const float*)d_in[15];
    const float* mean   = (const float*)d_in[16];
    const float* var    = (const float*)d_in[17];

    k_gemm<<<dim3(HW_ / 128, C3_ / 128, 4), 256>>>(hsi, lidar, hqkvw, hqkvb, lqkvw, lqkvb);
    k_dw  <<<4 * C3_, 128>>>(hdww, hdwb, ldww, ldwb);
    k_attn<<<dim3(HEADS_, B_, 2), 256>>>(temp1, temp2);
    k_fuse<<<dim3(HEADS_, B_), 64>>>(projw, projb, gamma, beta, mean, var);
    k_out <<<dim3(HW_ / 256, B_ * HEADS_, 2), 256>>>(hsi, lidar, (float*)d_out);
}

// round 5
// speedup vs baseline: 2.4843x; 2.4843x over previous
#include <cuda_runtime.h>
#include <cuda_bf16.h>
#include <math.h>
#include <cstdint>

#define B_    2
#define C_    512
#define C3_   1536
#define H_    128
#define W_    128
#define HW_   16384
#define HEADS_ 64
#define CH_   8
#define PLANE_ (C3_ * HW_)
#define TENSOR_ ((size_t)B_ * C_ * HW_)

// ---------------- scratch ----------------
__device__ float g_conv[4][PLANE_];
__device__ float g_dw[4][PLANE_];
__device__ float g_sumsq[2][B_][2][C_];
__device__ float g_attn[2][B_][HEADS_][64];
__device__ float g_a[2][B_][HEADS_][64];

// ---------------- helpers ----------------
static __device__ __forceinline__ uint32_t s2u(const void* p) {
    uint32_t a;
    asm("{ .reg .u64 t; cvta.to.shared.u64 t, %1; cvt.u32.u64 %0, t; }"
        : "=r"(a) : "l"(p));
    return a;
}
static __device__ __forceinline__ void cpasync16(uint32_t dst, const void* src) {
    asm volatile("cp.async.cg.shared.global [%0], [%1], 16;" :: "r"(dst), "l"(src));
}
static __device__ __forceinline__ void cp_commit() {
    asm volatile("cp.async.commit_group;" ::: "memory");
}
template <int N>
static __device__ __forceinline__ void cp_wait() {
    asm volatile("cp.async.wait_group %0;" :: "n"(N) : "memory");
}
static __device__ __forceinline__ void mma_tf32(float& d0, float& d1, float& d2, float& d3,
                                                uint32_t a0, uint32_t a1, uint32_t a2, uint32_t a3,
                                                uint32_t b0, uint32_t b1) {
    asm volatile("mma.sync.aligned.m16n8k8.row.col.f32.tf32.tf32.f32 "
                 "{%0,%1,%2,%3}, {%4,%5,%6,%7}, {%8,%9}, {%0,%1,%2,%3};"
                 : "+f"(d0), "+f"(d1), "+f"(d2), "+f"(d3)
                 : "r"(a0), "r"(a1), "r"(a2), "r"(a3), "r"(b0), "r"(b1));
}

// ---------------- K1: tf32 mma.sync GEMM  Y[m,n] = sum_k W[m,k] X[k,n] + bias[m] ----
// BM=128, BN=128, BK=16, 256 threads, 2-stage cp.async pipeline.
#define BK_    16
#define APAD_  20   // floats per A smem row (16 + 4 pad)
#define XPAD_  136  // floats per X smem row (128 + 8 pad)
#define KITERS (C_ / BK_)   // 32

__global__ __launch_bounds__(256, 2) void k_gemm_mma(
    const float* __restrict__ hsi, const float* __restrict__ lidar,
    const float* __restrict__ hw_w, const float* __restrict__ hw_b,
    const float* __restrict__ lw_w, const float* __restrict__ lw_b)
{
    __shared__ float As[2][128 * APAD_];   // 20480 B
    __shared__ float Xs[2][BK_ * XPAD_];   // 17408 B

    const int tid  = threadIdx.x;
    const int lane = tid & 31;
    const int wid  = tid >> 5;
    const int g    = lane >> 2;   // group id 0..7
    const int c    = lane & 3;    // thread-in-group 0..3

    const int mb  = blockIdx.z;
    const int mod = mb >> 1, bb = mb & 1;
    const float* Wm   = mod ? lw_w : hw_w;
    const float* bias = mod ? lw_b : hw_b;
    const float* X = (mod ? lidar : hsi) + (size_t)bb * C_ * HW_;
    float* Y = g_conv[mb];
    const int m0 = blockIdx.x * 128;   // m fastest -> CTAs sharing X run together
    const int n0 = blockIdx.y * 128;

    const int warp_m = (wid & 1) * 64;
    const int warp_n = (wid >> 1) * 32;

    // cp.async source/dest indices
    const int a_row0 = tid >> 2;        // 0..63 (+64 second pass)
    const int a_gr   = tid & 3;         // 16B granule in k
    const int x_k0   = tid >> 3;        // 0..31 -> two passes cover k 0..15
    const int x_gr   = tid & 7;         // 16B granule in n

    const uint32_t asb = s2u(&As[0][0]);
    const uint32_t xsb = s2u(&Xs[0][0]);

    float acc[4][4][4] = {};   // [mi][nj][frag]

    // stage loader
    auto load_stage = [&](int s, int k0) {
        #pragma unroll
        for (int i = 0; i < 2; i++) {
            int row = a_row0 + 64 * i;
            cpasync16(asb + (s * 128 * APAD_ + row * APAD_ + a_gr * 4) * 4,
                      &Wm[(size_t)(m0 + row) * C_ + k0 + a_gr * 4]);
        }
        #pragma unroll
        for (int i = 0; i < 2; i++) {
            int k = x_k0 + 32 * i;   // wait: x_k0 in 0..31 already covers 2*BK rows? no:
            (void)k;
        }
        // X tile: 16 rows x 128 cols = 512 granules of 16B; 256 threads x 2
        #pragma unroll
        for (int i = 0; i < 2; i++) {
            int idx = tid + 256 * i;
            int kk  = idx >> 5;        // 0..15
            int gr  = idx & 31;        // 0..31 granules of 4 floats
            cpasync16(xsb + (s * BK_ * XPAD_ + kk * XPAD_ + gr * 4) * 4,
                      &X[(size_t)(k0 + kk) * HW_ + n0 + gr * 4]);
        }
    };

    load_stage(0, 0);
    cp_commit();
    load_stage(1, BK_);
    cp_commit();

    for (int it = 0; it < KITERS; it++) {
        const int s = it & 1;
        cp_wait<1>();
        __syncthreads();

        const float* Ap = &As[s][0];
        const float* Xp = &Xs[s][0];
        #pragma unroll
        for (int ks = 0; ks < BK_; ks += 8) {
            uint32_t af[4][4], bf[4][2];
            #pragma unroll
            for (int i = 0; i < 4; i++) {
                int row = warp_m + 16 * i + g;
                af[i][0] = __float_as_uint(Ap[row * APAD_ + ks + c]);
                af[i][1] = __float_as_uint(Ap[(row + 8) * APAD_ + ks + c]);
                af[i][2] = __float_as_uint(Ap[row * APAD_ + ks + c + 4]);
                af[i][3] = __float_as_uint(Ap[(row + 8) * APAD_ + ks + c + 4]);
            }
            #pragma unroll
            for (int j = 0; j < 4; j++) {
                int col = warp_n + 8 * j + g;
                bf[j][0] = __float_as_uint(Xp[(ks + c) * XPAD_ + col]);
                bf[j][1] = __float_as_uint(Xp[(ks + c + 4) * XPAD_ + col]);
            }
            #pragma unroll
            for (int i = 0; i < 4; i++)
                #pragma unroll
                for (int j = 0; j < 4; j++)
                    mma_tf32(acc[i][j][0], acc[i][j][1], acc[i][j][2], acc[i][j][3],
                             af[i][0], af[i][1], af[i][2], af[i][3],
                             bf[j][0], bf[j][1]);
        }
        __syncthreads();
        if (it + 2 < KITERS) {
            load_stage(s, (it + 2) * BK_);
            cp_commit();
        } else {
            cp_commit();   // keep group count in sync for cp_wait<1>
        }
    }

    // epilogue: direct STG (float2 per fragment row), + bias
    #pragma unroll
    for (int i = 0; i < 4; i++) {
        const int r0 = m0 + warp_m + 16 * i + g;
        const float bi0 = bias[r0];
        const float bi1 = bias[r0 + 8];
        #pragma unroll
        for (int j = 0; j < 4; j++) {
            const int col = n0 + warp_n + 8 * j + 2 * c;
            *(float2*)&Y[(size_t)r0 * HW_ + col] =
                make_float2(acc[i][j][0] + bi0, acc[i][j][1] + bi0);
            *(float2*)&Y[(size_t)(r0 + 8) * HW_ + col] =
                make_float2(acc[i][j][2] + bi1, acc[i][j][3] + bi1);
        }
    }
}

// ---------------- K2: depthwise 3x3 + per-channel sum of squares ---
__global__ __launch_bounds__(128) void k_dw(
    const float* __restrict__ hdww, const float* __restrict__ hdwb,
    const float* __restrict__ ldww, const float* __restrict__ ldwb)
{
    int idx = blockIdx.x;
    int o   = idx % C3_;
    int mb  = idx / C3_;
    int mod = mb >> 1;
    const float* src = g_conv[mb] + (size_t)o * HW_;
    float*       dst = g_dw[mb]   + (size_t)o * HW_;
    const float* wp  = (mod ? ldww : hdww) + o * 9;
    float w[9];
    #pragma unroll
    for (int t = 0; t < 9; t++) w[t] = __ldg(&wp[t]);
    float bias = (mod ? ldwb : hdwb)[o];

    int x = threadIdx.x;
    bool xl = x > 0, xr = x < 127;
    float rm1[3] = {0.f, 0.f, 0.f};
    float r0[3], r1[3];
    r0[0] = xl ? src[x - 1] : 0.f;
    r0[1] = src[x];
    r0[2] = xr ? src[x + 1] : 0.f;
    float ssq = 0.f;
    for (int y = 0; y < H_; y++) {
        if (y < H_ - 1) {
            const float* s = src + (y + 1) * W_;
            r1[0] = xl ? s[x - 1] : 0.f;
            r1[1] = s[x];
            r1[2] = xr ? s[x + 1] : 0.f;
        } else {
            r1[0] = r1[1] = r1[2] = 0.f;
        }
        float v = bias
                + w[0] * rm1[0] + w[1] * rm1[1] + w[2] * rm1[2]
                + w[3] * r0[0]  + w[4] * r0[1]  + w[5] * r0[2]
                + w[6] * r1[0]  + w[7] * r1[1]  + w[8] * r1[2];
        dst[y * W_ + x] = v;
        ssq += v * v;
        rm1[0] = r0[0]; rm1[1] = r0[1]; rm1[2] = r0[2];
        r0[0]  = r1[0]; r0[1]  = r1[1]; r0[2]  = r1[2];
    }
    if (o < 2 * C_) {
        #pragma unroll
        for (int off = 16; off; off >>= 1)
            ssq += __shfl_down_sync(0xffffffffu, ssq, off);
        __shared__ float sw[4];
        if ((x & 31) == 0) sw[x >> 5] = ssq;
        __syncthreads();
        if (x == 0) {
            float t = sw[0] + sw[1] + sw[2] + sw[3];
            g_sumsq[mod][mb & 1][(o >= C_) ? 1 : 0][o & (C_ - 1)] = t;
        }
    }
}

// ---------------- K3: channel attention -------
__global__ __launch_bounds__(256) void k_attn(
    const float* __restrict__ temp1, const float* __restrict__ temp2)
{
    int h = blockIdx.x, bb = blockIdx.y, a = blockIdx.z;
    int qmod = a, kmod = 1 - a;
    const float* q  = g_dw[qmod * 2 + bb] + (size_t)(h * CH_) * HW_;
    const float* kk = g_dw[kmod * 2 + bb] + (size_t)(C_ + h * CH_) * HW_;
    int tid = threadIdx.x;
    float acc[8][8] = {};
    for (int n = tid; n < HW_; n += 256) {
        float qv[8], kv[8];
        #pragma unroll
        for (int c = 0; c < 8; c++) {
            qv[c] = q[(size_t)c * HW_ + n];
            kv[c] = kk[(size_t)c * HW_ + n];
        }
        #pragma unroll
        for (int c = 0; c < 8; c++)
            #pragma unroll
            for (int d = 0; d < 8; d++)
                acc[c][d] += qv[c] * kv[d];
    }
    __shared__ float red[8][64];
    int lane = tid & 31, wid = tid >> 5;
    #pragma unroll
    for (int c = 0; c < 8; c++)
        #pragma unroll
        for (int d = 0; d < 8; d++) {
            float v = acc[c][d];
            #pragma unroll
            for (int off = 16; off; off >>= 1)
                v += __shfl_down_sync(0xffffffffu, v, off);
            if (lane == 0) red[wid][c * 8 + d] = v;
        }
    __syncthreads();
    if (tid < 64) {
        float s = 0.f;
        #pragma unroll
        for (int wg = 0; wg < 8; wg++) s += red[wg][tid];
        int c = tid >> 3, d = tid & 7;
        float qn = fmaxf(sqrtf(g_sumsq[qmod][bb][0][h * CH_ + c]), 1e-12f);
        float kn = fmaxf(sqrtf(g_sumsq[kmod][bb][1][h * CH_ + d]), 1e-12f);
        float tmp = (a == 0 ? temp1 : temp2)[h];
        g_attn[a][bb][h][tid] = s / (qn * kn) * tmp;
    }
}

// ---------------- K4: score fusion + BN + ReLU + softmax ---------
__global__ __launch_bounds__(64) void k_fuse(
    const float* __restrict__ projw, const float* __restrict__ projb,
    const float* __restrict__ gamma, const float* __restrict__ beta,
    const float* __restrict__ mean,  const float* __restrict__ var)
{
    int o = blockIdx.x, bb = blockIdx.y;
    int tid = threadIdx.x;
    float s = projb[o];
    const float* w = projw + o * 128;
    #pragma unroll 8
    for (int i = 0; i < 64; i++) s += w[i]      * g_attn[0][bb][i][tid];
    #pragma unroll 8
    for (int i = 0; i < 64; i++) s += w[64 + i] * g_attn[1][bb][i][tid];
    s = (s - mean[o]) * rsqrtf(var[o] + 1e-5f) * gamma[o] + beta[o];
    s = fmaxf(s, 0.f);
    #pragma unroll
    for (int a = 0; a < 2; a++) {
        float v = s + g_attn[a][bb][o][tid];
        float m = v;
        #pragma unroll
        for (int off = 4; off; off >>= 1)
            m = fmaxf(m, __shfl_xor_sync(0xffffffffu, m, off, 8));
        float e = expf(v - m);
        float su = e;
        #pragma unroll
        for (int off = 4; off; off >>= 1)
            su += __shfl_xor_sync(0xffffffffu, su, off, 8);
        g_a[a][bb][o][tid] = e / su;
    }
}

// ---------------- K5: out = a @ v + v + x -----------------------
__global__ __launch_bounds__(256) void k_out(
    const float* __restrict__ hsi, const float* __restrict__ lidar,
    float* __restrict__ out)
{
    int mod = blockIdx.z;
    int bh  = blockIdx.y;
    int bb  = bh >> 6, h = bh & 63;
    int n   = blockIdx.x * 256 + threadIdx.x;
    __shared__ float a_s[64];
    if (threadIdx.x < 64)
        a_s[threadIdx.x] = g_a[mod][bb][h][threadIdx.x];
    __syncthreads();
    const float* v = g_dw[mod * 2 + bb] + (size_t)(2 * C_ + h * CH_) * HW_;
    const float* x = (mod ? lidar : hsi) + (size_t)(bb * C_ + h * CH_) * HW_;
    float* op = out + (size_t)mod * TENSOR_ + (size_t)(bb * C_ + h * CH_) * HW_;
    float vv[8];
    #pragma unroll
    for (int d = 0; d < 8; d++) vv[d] = v[(size_t)d * HW_ + n];
    #pragma unroll
    for (int c = 0; c < 8; c++) {
        float s = vv[c] + x[(size_t)c * HW_ + n];
        #pragma unroll
        for (int d = 0; d < 8; d++) s += a_s[c * 8 + d] * vv[d];
        op[(size_t)c * HW_ + n] = s;
    }
}

// ---------------- launch -----------------------------------------------------------
extern "C" void kernel_launch(void* const* d_in, const int* in_sizes, int n_in,
                              void* d_out, int out_size)
{
    const float* hsi    = (const float*)d_in[0];
    const float* lidar  = (const float*)d_in[1];
    const float* hqkvw  = (const float*)d_in[2];
    const float* hqkvb  = (const float*)d_in[3];
    const float* lqkvw  = (const float*)d_in[4];
    const float* lqkvb  = (const float*)d_in[5];
    const float* hdww   = (const float*)d_in[6];
    const float* hdwb   = (const float*)d_in[7];
    const float* ldww   = (const float*)d_in[8];
    const float* ldwb   = (const float*)d_in[9];
    const float* temp1  = (const float*)d_in[10];
    const float* temp2  = (const float*)d_in[11];
    const float* projw  = (const float*)d_in[12];
    const float* projb  = (const float*)d_in[13];
    const float* gamma  = (const float*)d_in[14];
    const float* beta   = (const float*)d_in[15];
    const float* mean   = (const float*)d_in[16];
    const float* var    = (const float*)d_in[17];

    k_gemm_mma<<<dim3(C3_ / 128, HW_ / 128, 4), 256>>>(hsi, lidar, hqkvw, hqkvb, lqkvw, lqkvb);
    k_dw  <<<4 * C3_, 128>>>(hdww, hdwb, ldww, ldwb);
    k_attn<<<dim3(HEADS_, B_, 2), 256>>>(temp1, temp2);
    k_fuse<<<dim3(HEADS_, B_), 64>>>(projw, projb, gamma, beta, mean, var);
    k_out <<<dim3(HW_ / 256, B_ * HEADS_, 2), 256>>>(hsi, lidar, (float*)d_out);
}

// round 6
// speedup vs baseline: 2.9111x; 1.1718x over previous
#include <cuda_runtime.h>
#include <cuda_bf16.h>
#include <math.h>
#include <cstdint>

#define B_    2
#define C_    512
#define C3_   1536
#define H_    128
#define W_    128
#define HW_   16384
#define HEADS_ 64
#define CH_   8
#define PLANE_ (C3_ * HW_)
#define TENSOR_ ((size_t)B_ * C_ * HW_)

// ---------------- scratch ----------------
__device__ float g_conv[4][PLANE_];
__device__ float g_dw[4][PLANE_];            // only v-channels written/used
__device__ float g_attn[2][B_][HEADS_][64];
__device__ float g_a[2][B_][HEADS_][64];

// ---------------- helpers ----------------
static __device__ __forceinline__ uint32_t s2u(const void* p) {
    uint32_t a;
    asm("{ .reg .u64 t; cvta.to.shared.u64 t, %1; cvt.u32.u64 %0, t; }"
        : "=r"(a) : "l"(p));
    return a;
}
static __device__ __forceinline__ void cpasync16(uint32_t dst, const void* src) {
    asm volatile("cp.async.cg.shared.global [%0], [%1], 16;" :: "r"(dst), "l"(src));
}
static __device__ __forceinline__ void cp_commit() {
    asm volatile("cp.async.commit_group;" ::: "memory");
}
template <int N>
static __device__ __forceinline__ void cp_wait() {
    asm volatile("cp.async.wait_group %0;" :: "n"(N) : "memory");
}
static __device__ __forceinline__ void mma_tf32(float& d0, float& d1, float& d2, float& d3,
                                                uint32_t a0, uint32_t a1, uint32_t a2, uint32_t a3,
                                                uint32_t b0, uint32_t b1) {
    asm volatile("mma.sync.aligned.m16n8k8.row.col.f32.tf32.tf32.f32 "
                 "{%0,%1,%2,%3}, {%4,%5,%6,%7}, {%8,%9}, {%0,%1,%2,%3};"
                 : "+f"(d0), "+f"(d1), "+f"(d2), "+f"(d3)
                 : "r"(a0), "r"(a1), "r"(a2), "r"(a3), "r"(b0), "r"(b1));
}

// ---------------- K1: tf32 mma.sync GEMM, 3-stage cp.async pipeline ----
#define BK_    16
#define APAD_  20
#define XPAD_  136
#define KITERS (C_ / BK_)   // 32
#define ST_    3
#define A_FLOATS (128 * APAD_)     // 2560
#define X_FLOATS (BK_ * XPAD_)     // 2176
#define GEMM_SMEM ((ST_ * (A_FLOATS + X_FLOATS)) * 4)   // 56832 B

__global__ __launch_bounds__(256, 2) void k_gemm_mma(
    const float* __restrict__ hsi, const float* __restrict__ lidar,
    const float* __restrict__ hw_w, const float* __restrict__ hw_b,
    const float* __restrict__ lw_w, const float* __restrict__ lw_b)
{
    extern __shared__ float smem_g[];
    float* Asm = smem_g;                     // ST_ stages of A
    float* Xsm = smem_g + ST_ * A_FLOATS;    // ST_ stages of X

    const int tid  = threadIdx.x;
    const int lane = tid & 31;
    const int wid  = tid >> 5;
    const int g    = lane >> 2;
    const int c    = lane & 3;

    const int mb  = blockIdx.z;
    const int mod = mb >> 1, bb = mb & 1;
    const float* Wm   = mod ? lw_w : hw_w;
    const float* bias = mod ? lw_b : hw_b;
    const float* X = (mod ? lidar : hsi) + (size_t)bb * C_ * HW_;
    float* Y = g_conv[mb];
    const int m0 = blockIdx.x * 128;
    const int n0 = blockIdx.y * 128;

    const int warp_m = (wid & 1) * 64;
    const int warp_n = (wid >> 1) * 32;

    const int a_row0 = tid >> 2;
    const int a_gr   = tid & 3;

    const uint32_t asb = s2u(Asm);
    const uint32_t xsb = s2u(Xsm);

    float acc[4][4][4] = {};

    auto load_stage = [&](int s, int k0) {
        #pragma unroll
        for (int i = 0; i < 2; i++) {
            int row = a_row0 + 64 * i;
            cpasync16(asb + (s * A_FLOATS + row * APAD_ + a_gr * 4) * 4,
                      &Wm[(size_t)(m0 + row) * C_ + k0 + a_gr * 4]);
        }
        #pragma unroll
        for (int i = 0; i < 2; i++) {
            int idx = tid + 256 * i;
            int kk  = idx >> 5;
            int gr  = idx & 31;
            cpasync16(xsb + (s * X_FLOATS + kk * XPAD_ + gr * 4) * 4,
                      &X[(size_t)(k0 + kk) * HW_ + n0 + gr * 4]);
        }
    };

    load_stage(0, 0);
    cp_commit();
    load_stage(1, BK_);
    cp_commit();

    for (int it = 0; it < KITERS; it++) {
        const int s = it % ST_;
        cp_wait<1>();
        __syncthreads();

        const float* Ap = &Asm[s * A_FLOATS];
        const float* Xp = &Xsm[s * X_FLOATS];
        #pragma unroll
        for (int ks = 0; ks < BK_; ks += 8) {
            uint32_t af[4][4], bf[4][2];
            #pragma unroll
            for (int i = 0; i < 4; i++) {
                int row = warp_m + 16 * i + g;
                af[i][0] = __float_as_uint(Ap[row * APAD_ + ks + c]);
                af[i][1] = __float_as_uint(Ap[(row + 8) * APAD_ + ks + c]);
                af[i][2] = __float_as_uint(Ap[row * APAD_ + ks + c + 4]);
                af[i][3] = __float_as_uint(Ap[(row + 8) * APAD_ + ks + c + 4]);
            }
            #pragma unroll
            for (int j = 0; j < 4; j++) {
                int col = warp_n + 8 * j + g;
                bf[j][0] = __float_as_uint(Xp[(ks + c) * XPAD_ + col]);
                bf[j][1] = __float_as_uint(Xp[(ks + c + 4) * XPAD_ + col]);
            }
            #pragma unroll
            for (int i = 0; i < 4; i++)
                #pragma unroll
                for (int j = 0; j < 4; j++)
                    mma_tf32(acc[i][j][0], acc[i][j][1], acc[i][j][2], acc[i][j][3],
                             af[i][0], af[i][1], af[i][2], af[i][3],
                             bf[j][0], bf[j][1]);
        }
        const int nxt = it + 2;
        if (nxt < KITERS) load_stage(nxt % ST_, nxt * BK_);
        cp_commit();
    }

    #pragma unroll
    for (int i = 0; i < 4; i++) {
        const int r0 = m0 + warp_m + 16 * i + g;
        const float bi0 = bias[r0];
        const float bi1 = bias[r0 + 8];
        #pragma unroll
        for (int j = 0; j < 4; j++) {
            const int col = n0 + warp_n + 8 * j + 2 * c;
            *(float2*)&Y[(size_t)r0 * HW_ + col] =
                make_float2(acc[i][j][0] + bi0, acc[i][j][1] + bi0);
            *(float2*)&Y[(size_t)(r0 + 8) * HW_ + col] =
                make_float2(acc[i][j][2] + bi1, acc[i][j][3] + bi1);
        }
    }
}

// ---------------- K2: depthwise 3x3, v-channels only ---
__global__ __launch_bounds__(128) void k_dw(
    const float* __restrict__ hdww, const float* __restrict__ hdwb,
    const float* __restrict__ ldww, const float* __restrict__ ldwb)
{
    int idx = blockIdx.x;            // mb*512 + ch
    int ch  = idx & 511;
    int mb  = idx >> 9;
    int mod = mb >> 1;
    int o   = 2 * C_ + ch;           // v plane
    const float* src = g_conv[mb] + (size_t)o * HW_;
    float*       dst = g_dw[mb]   + (size_t)o * HW_;
    const float* wp  = (mod ? ldww : hdww) + o * 9;
    float w[9];
    #pragma unroll
    for (int t = 0; t < 9; t++) w[t] = __ldg(&wp[t]);
    float bias = (mod ? ldwb : hdwb)[o];

    int x = threadIdx.x;
    bool xl = x > 0, xr = x < 127;
    float rm1[3] = {0.f, 0.f, 0.f};
    float r0[3], r1[3];
    r0[0] = xl ? src[x - 1] : 0.f;
    r0[1] = src[x];
    r0[2] = xr ? src[x + 1] : 0.f;
    for (int y = 0; y < H_; y++) {
        if (y < H_ - 1) {
            const float* s = src + (y + 1) * W_;
            r1[0] = xl ? s[x - 1] : 0.f;
            r1[1] = s[x];
            r1[2] = xr ? s[x + 1] : 0.f;
        } else {
            r1[0] = r1[1] = r1[2] = 0.f;
        }
        float v = bias
                + w[0] * rm1[0] + w[1] * rm1[1] + w[2] * rm1[2]
                + w[3] * r0[0]  + w[4] * r0[1]  + w[5] * r0[2]
                + w[6] * r1[0]  + w[7] * r1[1]  + w[8] * r1[2];
        dst[y * W_ + x] = v;
        rm1[0] = r0[0]; rm1[1] = r0[1]; rm1[2] = r0[2];
        r0[0]  = r1[0]; r0[1]  = r1[1]; r0[2]  = r1[2];
    }
}

// ---------------- K3: fused dwconv(q,k) + ssq + channel-attention dot --------------
// grid: (h=64, bb=2, a=2). 512 threads = 16 warps; warp w<8 -> q ch w (mod=a),
// warp w>=8 -> k ch w-8 (mod=1-a). q/k dw planes are dead after this kernel,
// so they are never written to gmem.
__global__ __launch_bounds__(512) void k_dwattn(
    const float* __restrict__ hdww, const float* __restrict__ hdwb,
    const float* __restrict__ ldww, const float* __restrict__ ldwb,
    const float* __restrict__ temp1, const float* __restrict__ temp2)
{
    __shared__ float rowbuf[16][132];
    __shared__ float sq[16];
    __shared__ float red[4][16][4];

    const int h = blockIdx.x, bb = blockIdx.y, a = blockIdx.z;
    const int tid = threadIdx.x;
    const int w = tid >> 5, lane = tid & 31;

    const int isk = w >> 3;                  // 0 = q plane, 1 = k plane
    const int ch  = w & 7;
    const int mod = isk ? (1 - a) : a;
    const int plane = (isk ? C_ : 0) + h * CH_ + ch;
    const float* src = g_conv[mod * 2 + bb] + (size_t)plane * HW_;
    const float* wp  = (mod ? ldww : hdww) + plane * 9;
    float wk[9];
    #pragma unroll
    for (int t = 0; t < 9; t++) wk[t] = __ldg(&wp[t]);
    const float bias = (mod ? ldwb : hdwb)[plane];

    const int x0 = lane * 4;

    float4 pv, cv, nv;
    float pl, pr, cl, cr, nl, nr;
    auto zero4 = [] { return make_float4(0.f, 0.f, 0.f, 0.f); };
    auto loadrow = [&](int y, float4& v, float& l, float& r) {
        if (y < 0 || y >= H_) { v = make_float4(0.f,0.f,0.f,0.f); l = 0.f; r = 0.f; return; }
        v = *(const float4*)&src[y * W_ + x0];
        l = __shfl_up_sync(0xffffffffu, v.w, 1);
        if (lane == 0) l = 0.f;
        r = __shfl_down_sync(0xffffffffu, v.x, 1);
        if (lane == 31) r = 0.f;
    };
    pv = zero4(); pl = pr = 0.f;
    loadrow(0, cv, cl, cr);
    loadrow(1, nv, nl, nr);

    // dot-phase identity
    const int xq  = tid & 127;
    const int blk = tid >> 7;                // 0..3
    const int c0  = (blk & 1) * 4;
    const int d0  = (blk >> 1) * 4;

    float ssq = 0.f;
    float acc[4][4] = {};

    for (int y = 0; y < H_; y++) {
        float o0 = bias
            + wk[0]*pl   + wk[1]*pv.x + wk[2]*pv.y
            + wk[3]*cl   + wk[4]*cv.x + wk[5]*cv.y
            + wk[6]*nl   + wk[7]*nv.x + wk[8]*nv.y;
        float o1 = bias
            + wk[0]*pv.x + wk[1]*pv.y + wk[2]*pv.z
            + wk[3]*cv.x + wk[4]*cv.y + wk[5]*cv.z
            + wk[6]*nv.x + wk[7]*nv.y + wk[8]*nv.z;
        float o2 = bias
            + wk[0]*pv.y + wk[1]*pv.z + wk[2]*pv.w
            + wk[3]*cv.y + wk[4]*cv.z + wk[5]*cv.w
            + wk[6]*nv.y + wk[7]*nv.z + wk[8]*nv.w;
        float o3 = bias
            + wk[0]*pv.z + wk[1]*pv.w + wk[2]*pr
            + wk[3]*cv.z + wk[4]*cv.w + wk[5]*cr
            + wk[6]*nv.z + wk[7]*nv.w + wk[8]*nr;

        __syncthreads();                     // previous row's dot phase done
        *(float4*)&rowbuf[w][x0] = make_float4(o0, o1, o2, o3);
        ssq += o0*o0 + o1*o1 + o2*o2 + o3*o3;

        // rotate window + prefetch y+2 (lands while dot phase runs)
        pv = cv; pl = cl; pr = cr;
        cv = nv; cl = nl; cr = nr;
        loadrow(y + 2, nv, nl, nr);

        __syncthreads();                     // rowbuf ready
        float qv[4], kv[4];
        #pragma unroll
        for (int i = 0; i < 4; i++) qv[i] = rowbuf[c0 + i][xq];
        #pragma unroll
        for (int j = 0; j < 4; j++) kv[j] = rowbuf[8 + d0 + j][xq];
        #pragma unroll
        for (int i = 0; i < 4; i++)
            #pragma unroll
            for (int j = 0; j < 4; j++)
                acc[i][j] += qv[i] * kv[j];
    }

    // plane sum-of-squares
    #pragma unroll
    for (int off = 16; off; off >>= 1)
        ssq += __shfl_down_sync(0xffffffffu, ssq, off);
    if (lane == 0) sq[w] = ssq;

    // reduce dot partials over x: warp = 32 consecutive x within one blk
    const int wsub = (tid >> 5) & 3;         // warp-within-blk
    #pragma unroll
    for (int i = 0; i < 4; i++)
        #pragma unroll
        for (int j = 0; j < 4; j++) {
            float v = acc[i][j];
            #pragma unroll
            for (int off = 16; off; off >>= 1)
                v += __shfl_down_sync(0xffffffffu, v, off);
            if (lane == 0) red[blk][i * 4 + j][wsub] = v;
        }
    __syncthreads();

    if (tid < 64) {
        int cc = tid >> 3, dd = tid & 7;
        int bq = (cc >> 2) + ((dd >> 2) << 1);
        int ii = cc & 3, jj = dd & 3;
        float dot = red[bq][ii * 4 + jj][0] + red[bq][ii * 4 + jj][1]
                  + red[bq][ii * 4 + jj][2] + red[bq][ii * 4 + jj][3];
        float qn = fmaxf(sqrtf(sq[cc]), 1e-12f);
        float kn = fmaxf(sqrtf(sq[8 + dd]), 1e-12f);
        float tmp = (a == 0 ? temp1 : temp2)[h];
        g_attn[a][bb][h][tid] = dot / (qn * kn) * tmp;
    }
}

// ---------------- K4: score fusion + BN + ReLU + softmax ---------
__global__ __launch_bounds__(64) void k_fuse(
    const float* __restrict__ projw, const float* __restrict__ projb,
    const float* __restrict__ gamma, const float* __restrict__ beta,
    const float* __restrict__ mean,  const float* __restrict__ var)
{
    int o = blockIdx.x, bb = blockIdx.y;
    int tid = threadIdx.x;
    float s = projb[o];
    const float* w = projw + o * 128;
    #pragma unroll 8
    for (int i = 0; i < 64; i++) s += w[i]      * g_attn[0][bb][i][tid];
    #pragma unroll 8
    for (int i = 0; i < 64; i++) s += w[64 + i] * g_attn[1][bb][i][tid];
    s = (s - mean[o]) * rsqrtf(var[o] + 1e-5f) * gamma[o] + beta[o];
    s = fmaxf(s, 0.f);
    #pragma unroll
    for (int a = 0; a < 2; a++) {
        float v = s + g_attn[a][bb][o][tid];
        float m = v;
        #pragma unroll
        for (int off = 4; off; off >>= 1)
            m = fmaxf(m, __shfl_xor_sync(0xffffffffu, m, off, 8));
        float e = expf(v - m);
        float su = e;
        #pragma unroll
        for (int off = 4; off; off >>= 1)
            su += __shfl_xor_sync(0xffffffffu, su, off, 8);
        g_a[a][bb][o][tid] = e / su;
    }
}

// ---------------- K5: out = a @ v + v + x -----------------------
__global__ __launch_bounds__(256) void k_out(
    const float* __restrict__ hsi, const float* __restrict__ lidar,
    float* __restrict__ out)
{
    int mod = blockIdx.z;
    int bh  = blockIdx.y;
    int bb  = bh >> 6, h = bh & 63;
    int n   = blockIdx.x * 256 + threadIdx.x;
    __shared__ float a_s[64];
    if (threadIdx.x < 64)
        a_s[threadIdx.x] = g_a[mod][bb][h][threadIdx.x];
    __syncthreads();
    const float* v = g_dw[mod * 2 + bb] + (size_t)(2 * C_ + h * CH_) * HW_;
    const float* x = (mod ? lidar : hsi) + (size_t)(bb * C_ + h * CH_) * HW_;
    float* op = out + (size_t)mod * TENSOR_ + (size_t)(bb * C_ + h * CH_) * HW_;
    float vv[8];
    #pragma unroll
    for (int d = 0; d < 8; d++) vv[d] = v[(size_t)d * HW_ + n];
    #pragma unroll
    for (int c = 0; c < 8; c++) {
        float s = vv[c] + x[(size_t)c * HW_ + n];
        #pragma unroll
        for (int d = 0; d < 8; d++) s += a_s[c * 8 + d] * vv[d];
        op[(size_t)c * HW_ + n] = s;
    }
}

// ---------------- launch -----------------------------------------------------------
extern "C" void kernel_launch(void* const* d_in, const int* in_sizes, int n_in,
                              void* d_out, int out_size)
{
    const float* hsi    = (const float*)d_in[0];
    const float* lidar  = (const float*)d_in[1];
    const float* hqkvw  = (const float*)d_in[2];
    const float* hqkvb  = (const float*)d_in[3];
    const float* lqkvw  = (const float*)d_in[4];
    const float* lqkvb  = (const float*)d_in[5];
    const float* hdww   = (const float*)d_in[6];
    const float* hdwb   = (const float*)d_in[7];
    const float* ldww   = (const float*)d_in[8];
    const float* ldwb   = (const float*)d_in[9];
    const float* temp1  = (const float*)d_in[10];
    const float* temp2  = (const float*)d_in[11];
    const float* projw  = (const float*)d_in[12];
    const float* projb  = (const float*)d_in[13];
    const float* gamma  = (const float*)d_in[14];
    const float* beta   = (const float*)d_in[15];
    const float* mean   = (const float*)d_in[16];
    const float* var    = (const float*)d_in[17];

    cudaFuncSetAttribute(k_gemm_mma, cudaFuncAttributeMaxDynamicSharedMemorySize,
                         GEMM_SMEM);
    k_gemm_mma<<<dim3(C3_ / 128, HW_ / 128, 4), 256, GEMM_SMEM>>>(
        hsi, lidar, hqkvw, hqkvb, lqkvw, lqkvb);
    k_dw    <<<4 * C_, 128>>>(hdww, hdwb, ldww, ldwb);
    k_dwattn<<<dim3(HEADS_, B_, 2), 512>>>(hdww, hdwb, ldww, ldwb, temp1, temp2);
    k_fuse  <<<dim3(HEADS_, B_), 64>>>(projw, projb, gamma, beta, mean, var);
    k_out   <<<dim3(HW_ / 256, B_ * HEADS_, 2), 256>>>(hsi, lidar, (float*)d_out);
}